// round 8
// baseline (speedup 1.0000x reference)
#include <cuda_runtime.h>
#include <mma.h>
#include <cstdint>

using namespace nvcuda;

#define N_ATOMS   100000
#define N_BONDS   200000
#define MAX_NB    6
#define ATOM_FDIM 133
#define BOND_FDIM 147
#define HIDDEN    256
#define N_MOLS    4096
#define MOL_FEAT  200
#define FFNN_HID  512
#define ENC_HID   256

// ---------------- scratch (device globals; no allocations allowed) ----------
__device__ float g_inputs[N_BONDS * HIDDEN];
__device__ float g_msgA[N_BONDS * HIDDEN];
__device__ float g_msgB[N_BONDS * HIDDEN];
__device__ float g_amsg[N_ATOMS * HIDDEN];
__device__ float g_ah[N_ATOMS * HIDDEN];
__device__ float g_sums[N_MOLS * HIDDEN];
__device__ float g_cnt[N_MOLS];
__device__ float g_molvec[N_MOLS * HIDDEN];
__device__ float g_hid[N_MOLS * FFNN_HID];

__device__ __forceinline__ float to_tf32(float x) {
    float y; asm("cvt.rna.tf32.f32 %0, %1;" : "=f"(y) : "f"(x)); return y;
}
__device__ __forceinline__ float4 cvt4(float4 v) {
    return make_float4(to_tf32(v.x), to_tf32(v.y), to_tf32(v.z), to_tf32(v.w));
}

// ---------------- wmma tf32 GEMM ---------------------------------------------
// out = relu(A @ W [+addend] [+bias]); W is [K,N] row-major.
// AMODE 0: A = A0 [M,K]
// AMODE 1: A = concat(A0 [M,K0], A1 [M,K-K0])
// AMODE 2: A[m,k] = A0[idxA[m]*K + k] - A1[idxR[m]*K + k]   (gather-diff)
// Tiles: BM=64, BN=256, BK=32 — one column tile spans the full N so each
// gathered A row is loaded exactly once (halves gather traffic vs BN=128x2).
// 8 warps, warp tile 32x64 (2x4 wmma frags). tf32 rounding once at staging.

#define BM 64
#define BN 256
#define AS_LD 36                  // A smem row stride
#define BS_LD 260                 // B smem row stride
#define SMEM_FLOATS (BM * AS_LD + 32 * BS_LD)   // 2304 + 8320 = 10624 -> 42496 B

template<int AMODE, bool VEC, bool HAS_ADDEND, bool HAS_BIAS, bool WRITE_PRE>
__global__ void __launch_bounds__(256)
gemm_wmma(const float* __restrict__ A0, const float* __restrict__ A1, int K0,
          const int* __restrict__ idxA, const int* __restrict__ idxR,
          const float* __restrict__ W,
          const float* __restrict__ addend, const float* __restrict__ bias,
          float* __restrict__ outPre, float* __restrict__ out,
          int M, int K, int N)
{
    extern __shared__ float smem[];
    float* As = smem;                    // [BM][AS_LD]
    float* Bs = smem + BM * AS_LD;       // [32][BS_LD]
    float* cbuf = smem;                  // reused post-mainloop (8x1024 <= 10624)

    __shared__ int sIA[BM], sIR[BM];

    const int tid  = threadIdx.x;
    const int wid  = tid >> 5;
    const int lane = tid & 31;
    const int wm   = wid & 1;            // 2 row groups of 32
    const int wn   = wid >> 1;           // 4 col groups of 64
    const int row0 = blockIdx.y * BM;
    const int col0 = blockIdx.x * BN;

    if (AMODE == 2) {
        if (tid < BM) {
            const int r = row0 + tid;
            sIA[tid] = (r < M) ? idxA[r] : 0;
            sIR[tid] = (r < M) ? idxR[r] : 0;
        }
        __syncthreads();
    }

    wmma::fragment<wmma::accumulator, 16, 16, 8, float> acc[2][4];
#pragma unroll
    for (int i = 0; i < 2; i++)
#pragma unroll
        for (int j = 0; j < 4; j++) wmma::fill_fragment(acc[i][j], 0.0f);

    const int KT = (K + 31) / 32;
    for (int t = 0; t < KT; t++) {
        const int k0g = t * 32;
        // ---- stage A tile [64][32]: 512 float4, 2 per thread ----
#pragma unroll
        for (int it = 0; it < 2; it++) {
            const int idx = tid + it * 256;
            const int m   = idx >> 3;          // 0..63
            const int q   = idx & 7;           // float4 slot in row
            const int mg  = row0 + m;
            const int kg  = k0g + q * 4;
            float4 v = make_float4(0.f, 0.f, 0.f, 0.f);
            if (AMODE == 2) {
                const float4 x = *(const float4*)(A0 + (long)sIA[m] * K + kg);
                const float4 y = *(const float4*)(A1 + (long)sIR[m] * K + kg);
                v = make_float4(x.x - y.x, x.y - y.y, x.z - y.z, x.w - y.w);
            } else if (VEC) {
                if (mg < M && kg + 4 <= K) {
                    if (AMODE == 0) v = *(const float4*)(A0 + (long)mg * K + kg);
                    else v = (kg < K0) ? *(const float4*)(A0 + (long)mg * K0 + kg)
                                       : *(const float4*)(A1 + (long)mg * (K - K0) + (kg - K0));
                }
            } else {
                if (mg < M) {
                    float e[4];
#pragma unroll
                    for (int c = 0; c < 4; c++) {
                        const int k = kg + c;
                        float x = 0.f;
                        if (k < K) {
                            if (AMODE == 0) x = A0[(long)mg * K + k];
                            else x = (k < K0) ? A0[(long)mg * K0 + k]
                                              : A1[(long)mg * (K - K0) + (k - K0)];
                        }
                        e[c] = x;
                    }
                    v = make_float4(e[0], e[1], e[2], e[3]);
                }
            }
            *(float4*)(As + m * AS_LD + q * 4) = cvt4(v);
        }
        // ---- stage B tile [32][256]: 2048 float4, 8 per thread ----
#pragma unroll
        for (int it = 0; it < 8; it++) {
            const int idx = tid + it * 256;
            const int k   = idx >> 6;          // 0..31
            const int q   = idx & 63;          // float4 slot in 256-float row
            const int kg2 = k0g + k;
            float4 v = make_float4(0.f, 0.f, 0.f, 0.f);
            if (kg2 < K) v = *(const float4*)(W + (long)kg2 * N + col0 + q * 4);
            *(float4*)(Bs + k * BS_LD + q * 4) = cvt4(v);
        }
        __syncthreads();

        // ---- mma: 4 k-steps of 8 (fragments pre-rounded, no cvt) ----
#pragma unroll
        for (int kk = 0; kk < 32; kk += 8) {
            wmma::fragment<wmma::matrix_a, 16, 16, 8, wmma::precision::tf32, wmma::row_major> af[2];
            wmma::fragment<wmma::matrix_b, 16, 16, 8, wmma::precision::tf32, wmma::row_major> bf[4];
#pragma unroll
            for (int i = 0; i < 2; i++)
                wmma::load_matrix_sync(af[i], As + (wm * 32 + i * 16) * AS_LD + kk, AS_LD);
#pragma unroll
            for (int j = 0; j < 4; j++)
                wmma::load_matrix_sync(bf[j], Bs + kk * BS_LD + wn * 64 + j * 16, BS_LD);
#pragma unroll
            for (int i = 0; i < 2; i++)
#pragma unroll
                for (int j = 0; j < 4; j++)
                    wmma::mma_sync(acc[i][j], af[i], bf[j], acc[i][j]);
        }
        __syncthreads();
    }

    // ---- epilogue: stage 32x32 halves per warp through smem ----
    float* cw = cbuf + wid * 1024;       // 32x32 floats per warp
#pragma unroll
    for (int h = 0; h < 2; h++) {
#pragma unroll
        for (int i = 0; i < 2; i++)
#pragma unroll
            for (int jj = 0; jj < 2; jj++)
                wmma::store_matrix_sync(cw + i * 16 * 32 + jj * 16,
                                        acc[i][h * 2 + jj], 32, wmma::mem_row_major);
        __syncwarp();
#pragma unroll
        for (int it = 0; it < 8; it++) {
            const int f4  = lane + it * 32;
            const int row = f4 >> 3;
            const int c4  = f4 & 7;
            const int rg  = row0 + wm * 32 + row;
            if (rg < M) {
                const int cg = col0 + wn * 64 + h * 32 + c4 * 4;
                float4 v = *(float4*)(cw + row * 32 + c4 * 4);
                const long base = (long)rg * N + cg;
                if (HAS_ADDEND) {
                    const float4 a = *(const float4*)(addend + base);
                    v.x += a.x; v.y += a.y; v.z += a.z; v.w += a.w;
                }
                if (HAS_BIAS) {
                    const float4 b = *(const float4*)(bias + cg);
                    v.x += b.x; v.y += b.y; v.z += b.z; v.w += b.w;
                }
                if (WRITE_PRE) *(float4*)(outPre + base) = v;
                *(float4*)(out + base) =
                    make_float4(fmaxf(v.x, 0.f), fmaxf(v.y, 0.f), fmaxf(v.z, 0.f), fmaxf(v.w, 0.f));
            }
        }
        __syncwarp();
    }
}

// ---------------- a_message[a] = sum_j message[a2b[a][j]] --------------------
__global__ void amsg_kernel(const float* __restrict__ msg,
                            const int* __restrict__ a2b,
                            float* __restrict__ amsg)
{
    const int t    = blockIdx.x * blockDim.x + threadIdx.x;
    const int atom = t >> 6;
    const int c4   = (t & 63) * 4;
    if (atom >= N_ATOMS) return;
    float4 s = make_float4(0.f, 0.f, 0.f, 0.f);
#pragma unroll
    for (int j = 0; j < MAX_NB; j++) {
        const int b = a2b[atom * MAX_NB + j];
        const float4 v = *(const float4*)(msg + (long)b * HIDDEN + c4);
        s.x += v.x; s.y += v.y; s.z += v.z; s.w += v.w;
    }
    *(float4*)(amsg + (long)atom * HIDDEN + c4) = s;
}

// ---------------- segment sum + mean ----------------------------------------
__global__ void seg_kernel(const float* __restrict__ ah,
                           const int* __restrict__ a2m,
                           float* __restrict__ sums,
                           float* __restrict__ cnt)
{
    const int t    = blockIdx.x * blockDim.x + threadIdx.x;
    const int atom = t >> 8;
    const int c    = t & 255;
    if (atom >= N_ATOMS) return;
    const int m = a2m[atom];
    atomicAdd(&sums[(long)m * HIDDEN + c], ah[(long)atom * HIDDEN + c]);
    if (c == 0) atomicAdd(&cnt[m], 1.0f);
}

__global__ void divide_kernel(const float* __restrict__ sums,
                              const float* __restrict__ cnt,
                              float* __restrict__ molvec)
{
    const int t = blockIdx.x * blockDim.x + threadIdx.x;
    if (t >= N_MOLS * HIDDEN) return;
    molvec[t] = sums[t] / fmaxf(cnt[t >> 8], 1.0f);
}

// ---------------- launch -----------------------------------------------------
extern "C" void kernel_launch(void* const* d_in, const int* in_sizes, int n_in,
                              void* d_out, int out_size)
{
    const float* f_atoms      = (const float*)d_in[0];
    const float* f_bonds      = (const float*)d_in[1];
    const int*   a2b          = (const int*)  d_in[2];
    const int*   b2a          = (const int*)  d_in[3];
    const int*   b2revb       = (const int*)  d_in[4];
    const int*   atom2mol     = (const int*)  d_in[5];
    const float* mol_features = (const float*)d_in[6];
    const float* W_i          = (const float*)d_in[7];
    const float* W_h          = (const float*)d_in[8];
    const float* W_o_w        = (const float*)d_in[9];
    const float* W_o_b        = (const float*)d_in[10];
    const float* W1           = (const float*)d_in[11];
    const float* b1           = (const float*)d_in[12];
    const float* W2           = (const float*)d_in[13];
    const float* b2           = (const float*)d_in[14];
    float* out = (float*)d_out;

    float *inputs, *msgA, *msgB, *amsg, *ah, *sums, *cnt, *molvec, *hid;
    cudaGetSymbolAddress((void**)&inputs, g_inputs);
    cudaGetSymbolAddress((void**)&msgA,   g_msgA);
    cudaGetSymbolAddress((void**)&msgB,   g_msgB);
    cudaGetSymbolAddress((void**)&amsg,   g_amsg);
    cudaGetSymbolAddress((void**)&ah,     g_ah);
    cudaGetSymbolAddress((void**)&sums,   g_sums);
    cudaGetSymbolAddress((void**)&cnt,    g_cnt);
    cudaGetSymbolAddress((void**)&molvec, g_molvec);
    cudaGetSymbolAddress((void**)&hid,    g_hid);

    const size_t smemBytes = SMEM_FLOATS * sizeof(float);   // 42496
    const dim3 gBond(HIDDEN / BN, (N_BONDS + BM - 1) / BM);   // (1, 3125)
    const dim3 gAtom(HIDDEN / BN, (N_ATOMS + BM - 1) / BM);   // (1, 1563)
    const int  amsgBlocks = (N_ATOMS * 64 + 255) / 256;
    const int  segBlocks  = (N_ATOMS * 256) / 256;

    // 1) inputs = f_bonds @ W_i ; msgA = relu(inputs)
    gemm_wmma<0, false, false, false, true><<<gBond, 256, smemBytes>>>(
        f_bonds, nullptr, 0, nullptr, nullptr, W_i,
        nullptr, nullptr, inputs, msgA, N_BONDS, BOND_FDIM, HIDDEN);

    // 2) depth iter 1: msgA -> msgB
    amsg_kernel<<<amsgBlocks, 256>>>(msgA, a2b, amsg);
    gemm_wmma<2, true, true, false, false><<<gBond, 256, smemBytes>>>(
        amsg, msgA, 0, b2a, b2revb, W_h,
        inputs, nullptr, nullptr, msgB, N_BONDS, HIDDEN, HIDDEN);

    // 3) depth iter 2: msgB -> msgA
    amsg_kernel<<<amsgBlocks, 256>>>(msgB, a2b, amsg);
    gemm_wmma<2, true, true, false, false><<<gBond, 256, smemBytes>>>(
        amsg, msgB, 0, b2a, b2revb, W_h,
        inputs, nullptr, nullptr, msgA, N_BONDS, HIDDEN, HIDDEN);

    // 4) final aggregation
    amsg_kernel<<<amsgBlocks, 256>>>(msgA, a2b, amsg);

    // 5) atom_hiddens = relu([f_atoms | amsg] @ W_o_w + W_o_b)
    gemm_wmma<1, false, false, true, false><<<gAtom, 256, smemBytes>>>(
        f_atoms, amsg, ATOM_FDIM, nullptr, nullptr, W_o_w,
        nullptr, W_o_b, nullptr, ah, N_ATOMS, ATOM_FDIM + HIDDEN, HIDDEN);

    // 6) per-molecule mean pool
    cudaMemsetAsync(sums, 0, (size_t)N_MOLS * HIDDEN * sizeof(float));
    cudaMemsetAsync(cnt,  0, (size_t)N_MOLS * sizeof(float));
    seg_kernel<<<segBlocks, 256>>>(ah, atom2mol, sums, cnt);
    divide_kernel<<<(N_MOLS * HIDDEN + 255) / 256, 256>>>(sums, cnt, molvec);

    // 7) FFNN layer 1: hid = relu([molvec | mol_features] @ W1 + b1)
    gemm_wmma<1, true, false, true, false><<<dim3(FFNN_HID / BN, N_MOLS / BM), 256, smemBytes>>>(
        molvec, mol_features, HIDDEN, nullptr, nullptr, W1,
        nullptr, b1, nullptr, hid, N_MOLS, HIDDEN + MOL_FEAT, FFNN_HID);

    // 8) FFNN layer 2: out = relu(hid @ W2 + b2)
    gemm_wmma<0, true, false, true, false><<<dim3(ENC_HID / BN, N_MOLS / BM), 256, smemBytes>>>(
        hid, nullptr, 0, nullptr, nullptr, W2,
        nullptr, b2, nullptr, out, N_MOLS, FFNN_HID, ENC_HID);
}

// round 11
// speedup vs baseline: 1.0968x; 1.0968x over previous
#include <cuda_runtime.h>
#include <mma.h>
#include <cstdint>

using namespace nvcuda;

#define N_ATOMS   100000
#define N_BONDS   200000
#define MAX_NB    6
#define ATOM_FDIM 133
#define BOND_FDIM 147
#define HIDDEN    256
#define N_MOLS    4096
#define MOL_FEAT  200
#define FFNN_HID  512
#define ENC_HID   256

// padded K dims (multiples of 16 floats)
#define FB_KP   160   // f_bonds 147 -> 160
#define AIN_KP  400   // 133+256=389 -> 400
#define X_KP    464   // 256+200=456 -> 464

// ---------------- scratch (device globals; no allocations allowed) ----------
__device__ float g_inputs[N_BONDS * HIDDEN];
__device__ float g_msgA[N_BONDS * HIDDEN];
__device__ float g_msgB[N_BONDS * HIDDEN];
__device__ float g_T[N_BONDS * HIDDEN];
__device__ float g_U[N_ATOMS * HIDDEN];
__device__ float g_amsg[N_ATOMS * HIDDEN];
__device__ float g_ah[N_ATOMS * HIDDEN];
__device__ float g_sums[N_MOLS * HIDDEN];
__device__ float g_cnt[N_MOLS];
__device__ float g_molvec[N_MOLS * HIDDEN];
__device__ float g_hid[N_MOLS * FFNN_HID];
__device__ float g_FB[N_BONDS * FB_KP];
__device__ float g_AIN[N_ATOMS * AIN_KP];
__device__ float g_X[N_MOLS * X_KP];
__device__ float g_WiR[FB_KP * HIDDEN];
__device__ float g_WhR[HIDDEN * HIDDEN];
__device__ float g_WoR[AIN_KP * HIDDEN];
__device__ float g_W1R[X_KP * FFNN_HID];
__device__ float g_W2R[FFNN_HID * ENC_HID];

__device__ __forceinline__ float to_tf32(float x) {
    float y; asm("cvt.rna.tf32.f32 %0, %1;" : "=f"(y) : "f"(x)); return y;
}

__device__ __forceinline__ void cp16(uint32_t dst, const float* src, uint32_t szok) {
    asm volatile("cp.async.ca.shared.global [%0], [%1], 16, %2;"
                 :: "r"(dst), "l"(src), "r"(szok) : "memory");
}

// ---------------- dense cp.async wmma tf32 GEMM ------------------------------
// out = act(A @ W [+bias]); A [M][K] 16B-aligned rows, K % 16 == 0, W [K][N].
// Operands are pre-rounded to tf32 by their producers. BM=128 BN=128 BK=16,
// 2-stage cp.async double buffer, 8 warps, warp tile 32x64.
#define AS_LD 20
#define BS_LD 132
#define AS_STRIDE (128 * AS_LD)            // 2560 floats per A stage
#define BS_STRIDE (16 * BS_LD)             // 2112 floats per B stage
#define GEMM_SMEM_FLOATS (2 * AS_STRIDE + 2 * BS_STRIDE)   // 9344 -> 37376 B

template<bool HAS_BIAS, bool WRITE_PRE, bool DO_RELU, bool ROUND_OUT>
__global__ void __launch_bounds__(256)
gemm_ca(const float* __restrict__ A, const float* __restrict__ W,
        const float* __restrict__ bias,
        float* __restrict__ outPre, float* __restrict__ out,
        int M, int K, int N)
{
    extern __shared__ float smem[];
    float* AsBase = smem;                       // [2][128][AS_LD]
    float* BsBase = smem + 2 * AS_STRIDE;       // [2][16][BS_LD]
    float* cbuf   = smem;                       // reused post-mainloop (8192 floats)
    const uint32_t s_base = (uint32_t)__cvta_generic_to_shared(smem);

    const int tid  = threadIdx.x;
    const int wid  = tid >> 5;
    const int lane = tid & 31;
    const int wm   = wid & 3;                   // 4 row groups of 32
    const int wn   = wid >> 2;                  // 2 col groups of 64
    const int row0 = blockIdx.y * 128;
    const int col0 = blockIdx.x * 128;

    // per-thread cp.async chunk coords
    // A: chunk c in [0,512): m=c>>2, q=c&3  -> thread handles c=tid, tid+256
    const int am0 = tid >> 2, aq0 = tid & 3;
    const int am1 = (tid + 256) >> 2, aq1 = (tid + 256) & 3;
    // B: chunk c in [0,512): k=c>>5, q=c&31
    const int bk0 = tid >> 5, bq0 = tid & 31;
    const int bk1 = (tid + 256) >> 5, bq1 = (tid + 256) & 31;

    wmma::fragment<wmma::accumulator, 16, 16, 8, float> acc[2][4];
#pragma unroll
    for (int i = 0; i < 2; i++)
#pragma unroll
        for (int j = 0; j < 4; j++) wmma::fill_fragment(acc[i][j], 0.0f);

    const int KT = K / 16;

    auto issue = [&](int t, int buf) {
        const int k0g = t * 16;
        const uint32_t aBase = s_base + (uint32_t)(buf * AS_STRIDE) * 4u;
        const uint32_t bBase = s_base + (uint32_t)(2 * AS_STRIDE + buf * BS_STRIDE) * 4u;
        // A tile [128][16]
        {
            const int mg = row0 + am0;
            cp16(aBase + (uint32_t)(am0 * AS_LD + aq0 * 4) * 4u,
                 A + (long)mg * K + k0g + aq0 * 4, (mg < M) ? 16u : 0u);
        }
        {
            const int mg = row0 + am1;
            cp16(aBase + (uint32_t)(am1 * AS_LD + aq1 * 4) * 4u,
                 A + (long)mg * K + k0g + aq1 * 4, (mg < M) ? 16u : 0u);
        }
        // B tile [16][128] (W rows padded -> always in bounds)
        cp16(bBase + (uint32_t)(bk0 * BS_LD + bq0 * 4) * 4u,
             W + (long)(k0g + bk0) * N + col0 + bq0 * 4, 16u);
        cp16(bBase + (uint32_t)(bk1 * BS_LD + bq1 * 4) * 4u,
             W + (long)(k0g + bk1) * N + col0 + bq1 * 4, 16u);
    };

    issue(0, 0);
    asm volatile("cp.async.commit_group;" ::: "memory");

    for (int t = 0; t < KT; t++) {
        if (t + 1 < KT) {
            issue(t + 1, (t + 1) & 1);
            asm volatile("cp.async.commit_group;" ::: "memory");
            asm volatile("cp.async.wait_group 1;" ::: "memory");
        } else {
            asm volatile("cp.async.wait_group 0;" ::: "memory");
        }
        __syncthreads();

        const float* As = AsBase + (t & 1) * AS_STRIDE;
        const float* Bs = BsBase + (t & 1) * BS_STRIDE;
#pragma unroll
        for (int kk = 0; kk < 16; kk += 8) {
            wmma::fragment<wmma::matrix_a, 16, 16, 8, wmma::precision::tf32, wmma::row_major> af[2];
            wmma::fragment<wmma::matrix_b, 16, 16, 8, wmma::precision::tf32, wmma::row_major> bf[4];
#pragma unroll
            for (int i = 0; i < 2; i++)
                wmma::load_matrix_sync(af[i], As + (wm * 32 + i * 16) * AS_LD + kk, AS_LD);
#pragma unroll
            for (int j = 0; j < 4; j++)
                wmma::load_matrix_sync(bf[j], Bs + kk * BS_LD + wn * 64 + j * 16, BS_LD);
#pragma unroll
            for (int i = 0; i < 2; i++)
#pragma unroll
                for (int j = 0; j < 4; j++)
                    wmma::mma_sync(acc[i][j], af[i], bf[j], acc[i][j]);
        }
        __syncthreads();
    }

    // ---- epilogue: stage 32x32 halves per warp through smem ----
    float* cw = cbuf + wid * 1024;
#pragma unroll
    for (int h = 0; h < 2; h++) {
#pragma unroll
        for (int i = 0; i < 2; i++)
#pragma unroll
            for (int jj = 0; jj < 2; jj++)
                wmma::store_matrix_sync(cw + i * 16 * 32 + jj * 16,
                                        acc[i][h * 2 + jj], 32, wmma::mem_row_major);
        __syncwarp();
#pragma unroll
        for (int it = 0; it < 8; it++) {
            const int f4  = lane + it * 32;
            const int row = f4 >> 3;
            const int c4  = f4 & 7;
            const int rg  = row0 + wm * 32 + row;
            if (rg < M) {
                const int cg = col0 + wn * 64 + h * 32 + c4 * 4;
                float4 v = *(float4*)(cw + row * 32 + c4 * 4);
                const long base = (long)rg * N + cg;
                if (HAS_BIAS) {
                    const float4 b = *(const float4*)(bias + cg);
                    v.x += b.x; v.y += b.y; v.z += b.z; v.w += b.w;
                }
                if (WRITE_PRE) *(float4*)(outPre + base) = v;
                if (DO_RELU) {
                    v = make_float4(fmaxf(v.x, 0.f), fmaxf(v.y, 0.f),
                                    fmaxf(v.z, 0.f), fmaxf(v.w, 0.f));
                }
                if (ROUND_OUT)
                    v = make_float4(to_tf32(v.x), to_tf32(v.y), to_tf32(v.z), to_tf32(v.w));
                *(float4*)(out + base) = v;
            }
        }
        __syncwarp();
    }
}

// ---------------- weight pad+round: dst[Kp][N], zeros beyond K --------------
__global__ void wpad_kernel(float* __restrict__ dst, const float* __restrict__ W,
                            int K, int N, int Kp)
{
    const int idx = blockIdx.x * blockDim.x + threadIdx.x;
    if (idx >= Kp * N) return;
    const int k = idx / N;
    dst[idx] = (k < K) ? to_tf32(W[idx]) : 0.f;   // idx = k*N + n valid when k<K
}

// ---------------- pack rows: dst[M][Kp] = round([s0 | s1 | 0pad]) -----------
__global__ void pack2_kernel(float* __restrict__ dst,
                             const float* __restrict__ s0,
                             const float* __restrict__ s1,
                             int M, int K0, int K1, int Kp)
{
    const int idx = blockIdx.x * blockDim.x + threadIdx.x;
    const int kp4 = Kp >> 2;
    if (idx >= M * kp4) return;
    const int m = idx / kp4;
    const int k = (idx - m * kp4) * 4;
    float e[4];
#pragma unroll
    for (int c = 0; c < 4; c++) {
        const int kk = k + c;
        float v = 0.f;
        if (kk < K0) v = s0[(long)m * K0 + kk];
        else if (kk < K0 + K1) v = s1[(long)m * K1 + (kk - K0)];
        e[c] = to_tf32(v);
    }
    *(float4*)(dst + (long)m * Kp + k) = make_float4(e[0], e[1], e[2], e[3]);
}

// ---------------- a_message[a] = round(sum_j message[a2b[a][j]]) -------------
__global__ void amsg_kernel(const float* __restrict__ msg,
                            const int* __restrict__ a2b,
                            float* __restrict__ amsg)
{
    const int t    = blockIdx.x * blockDim.x + threadIdx.x;
    const int atom = t >> 6;
    const int c4   = (t & 63) * 4;
    if (atom >= N_ATOMS) return;
    float4 s = make_float4(0.f, 0.f, 0.f, 0.f);
#pragma unroll
    for (int j = 0; j < MAX_NB; j++) {
        const int b = a2b[atom * MAX_NB + j];
        const float4 v = *(const float4*)(msg + (long)b * HIDDEN + c4);
        s.x += v.x; s.y += v.y; s.z += v.z; s.w += v.w;
    }
    s = make_float4(to_tf32(s.x), to_tf32(s.y), to_tf32(s.z), to_tf32(s.w));
    *(float4*)(amsg + (long)atom * HIDDEN + c4) = s;
}

// ---------------- msg' = round(relu(inputs + U[b2a] - T[b2revb])) ------------
__global__ void combine_kernel(const float* __restrict__ inputs,
                               const float* __restrict__ U,
                               const float* __restrict__ T,
                               const int* __restrict__ b2a,
                               const int* __restrict__ b2revb,
                               float* __restrict__ msg)
{
    const int t    = blockIdx.x * blockDim.x + threadIdx.x;
    const int bond = t >> 6;
    const int c4   = (t & 63) * 4;
    if (bond >= N_BONDS) return;
    const int ai = b2a[bond];
    const int rb = b2revb[bond];
    const float4 u  = *(const float4*)(U + (long)ai * HIDDEN + c4);
    const float4 tv = *(const float4*)(T + (long)rb * HIDDEN + c4);
    const float4 ip = *(const float4*)(inputs + (long)bond * HIDDEN + c4);
    float4 v = make_float4(ip.x + u.x - tv.x, ip.y + u.y - tv.y,
                           ip.z + u.z - tv.z, ip.w + u.w - tv.w);
    v = make_float4(to_tf32(fmaxf(v.x, 0.f)), to_tf32(fmaxf(v.y, 0.f)),
                    to_tf32(fmaxf(v.z, 0.f)), to_tf32(fmaxf(v.w, 0.f)));
    *(float4*)(msg + (long)bond * HIDDEN + c4) = v;
}

// ---------------- segment sum + mean ----------------------------------------
__global__ void seg_kernel(const float* __restrict__ ah,
                           const int* __restrict__ a2m,
                           float* __restrict__ sums,
                           float* __restrict__ cnt)
{
    const int t    = blockIdx.x * blockDim.x + threadIdx.x;
    const int atom = t >> 8;
    const int c    = t & 255;
    if (atom >= N_ATOMS) return;
    const int m = a2m[atom];
    atomicAdd(&sums[(long)m * HIDDEN + c], ah[(long)atom * HIDDEN + c]);
    if (c == 0) atomicAdd(&cnt[m], 1.0f);
}

__global__ void divide_kernel(const float* __restrict__ sums,
                              const float* __restrict__ cnt,
                              float* __restrict__ molvec)
{
    const int t = blockIdx.x * blockDim.x + threadIdx.x;
    if (t >= N_MOLS * HIDDEN) return;
    molvec[t] = sums[t] / fmaxf(cnt[t >> 8], 1.0f);
}

// ---------------- launch -----------------------------------------------------
extern "C" void kernel_launch(void* const* d_in, const int* in_sizes, int n_in,
                              void* d_out, int out_size)
{
    const float* f_atoms      = (const float*)d_in[0];
    const float* f_bonds      = (const float*)d_in[1];
    const int*   a2b          = (const int*)  d_in[2];
    const int*   b2a          = (const int*)  d_in[3];
    const int*   b2revb       = (const int*)  d_in[4];
    const int*   atom2mol     = (const int*)  d_in[5];
    const float* mol_features = (const float*)d_in[6];
    const float* W_i          = (const float*)d_in[7];
    const float* W_h          = (const float*)d_in[8];
    const float* W_o_w        = (const float*)d_in[9];
    const float* W_o_b        = (const float*)d_in[10];
    const float* W1           = (const float*)d_in[11];
    const float* b1           = (const float*)d_in[12];
    const float* W2           = (const float*)d_in[13];
    const float* b2           = (const float*)d_in[14];
    float* out = (float*)d_out;

    float *inputs, *msgA, *msgB, *T, *U, *amsg, *ah, *sums, *cnt, *molvec, *hid;
    float *FB, *AIN, *X, *WiR, *WhR, *WoR, *W1R, *W2R;
    cudaGetSymbolAddress((void**)&inputs, g_inputs);
    cudaGetSymbolAddress((void**)&msgA,   g_msgA);
    cudaGetSymbolAddress((void**)&msgB,   g_msgB);
    cudaGetSymbolAddress((void**)&T,      g_T);
    cudaGetSymbolAddress((void**)&U,      g_U);
    cudaGetSymbolAddress((void**)&amsg,   g_amsg);
    cudaGetSymbolAddress((void**)&ah,     g_ah);
    cudaGetSymbolAddress((void**)&sums,   g_sums);
    cudaGetSymbolAddress((void**)&cnt,    g_cnt);
    cudaGetSymbolAddress((void**)&molvec, g_molvec);
    cudaGetSymbolAddress((void**)&hid,    g_hid);
    cudaGetSymbolAddress((void**)&FB,     g_FB);
    cudaGetSymbolAddress((void**)&AIN,    g_AIN);
    cudaGetSymbolAddress((void**)&X,      g_X);
    cudaGetSymbolAddress((void**)&WiR,    g_WiR);
    cudaGetSymbolAddress((void**)&WhR,    g_WhR);
    cudaGetSymbolAddress((void**)&WoR,    g_WoR);
    cudaGetSymbolAddress((void**)&W1R,    g_W1R);
    cudaGetSymbolAddress((void**)&W2R,    g_W2R);

    const size_t gsm = GEMM_SMEM_FLOATS * sizeof(float);   // 37376 B
    const int amsgBlocks = (N_ATOMS * 64 + 255) / 256;
    const int combBlocks = (N_BONDS * 64 + 255) / 256;
    const int segBlocks  = (N_ATOMS * 256) / 256;

    // ---- weight pad+round ----
    wpad_kernel<<<(FB_KP * HIDDEN + 255) / 256, 256>>>(WiR, W_i, BOND_FDIM, HIDDEN, FB_KP);
    wpad_kernel<<<(HIDDEN * HIDDEN + 255) / 256, 256>>>(WhR, W_h, HIDDEN, HIDDEN, HIDDEN);
    wpad_kernel<<<(AIN_KP * HIDDEN + 255) / 256, 256>>>(WoR, W_o_w, ATOM_FDIM + HIDDEN, HIDDEN, AIN_KP);
    wpad_kernel<<<(X_KP * FFNN_HID + 255) / 256, 256>>>(W1R, W1, HIDDEN + MOL_FEAT, FFNN_HID, X_KP);
    wpad_kernel<<<(FFNN_HID * ENC_HID + 255) / 256, 256>>>(W2R, W2, FFNN_HID, ENC_HID, FFNN_HID);

    // ---- pack f_bonds ----
    pack2_kernel<<<(N_BONDS * (FB_KP / 4) + 255) / 256, 256>>>(
        FB, f_bonds, nullptr, N_BONDS, BOND_FDIM, 0, FB_KP);

    // 1) inputs = FB @ WiR (pre-relu kept); msgA = round(relu(inputs))
    gemm_ca<false, true, true, true><<<dim3(2, (N_BONDS + 127) / 128), 256, gsm>>>(
        FB, WiR, nullptr, inputs, msgA, N_BONDS, FB_KP, HIDDEN);

    // ---- iter 1: msgA -> msgB ----
    amsg_kernel<<<amsgBlocks, 256>>>(msgA, a2b, amsg);
    gemm_ca<false, false, false, false><<<dim3(2, (N_ATOMS + 127) / 128), 256, gsm>>>(
        amsg, WhR, nullptr, nullptr, U, N_ATOMS, HIDDEN, HIDDEN);
    gemm_ca<false, false, false, false><<<dim3(2, (N_BONDS + 127) / 128), 256, gsm>>>(
        msgA, WhR, nullptr, nullptr, T, N_BONDS, HIDDEN, HIDDEN);
    combine_kernel<<<combBlocks, 256>>>(inputs, U, T, b2a, b2revb, msgB);

    // ---- iter 2: msgB -> msgA ----
    amsg_kernel<<<amsgBlocks, 256>>>(msgB, a2b, amsg);
    gemm_ca<false, false, false, false><<<dim3(2, (N_ATOMS + 127) / 128), 256, gsm>>>(
        amsg, WhR, nullptr, nullptr, U, N_ATOMS, HIDDEN, HIDDEN);
    gemm_ca<false, false, false, false><<<dim3(2, (N_BONDS + 127) / 128), 256, gsm>>>(
        msgB, WhR, nullptr, nullptr, T, N_BONDS, HIDDEN, HIDDEN);
    combine_kernel<<<combBlocks, 256>>>(inputs, U, T, b2a, b2revb, msgA);

    // ---- final aggregation + readout ----
    amsg_kernel<<<amsgBlocks, 256>>>(msgA, a2b, amsg);
    pack2_kernel<<<(N_ATOMS * (AIN_KP / 4) + 255) / 256, 256>>>(
        AIN, f_atoms, amsg, N_ATOMS, ATOM_FDIM, HIDDEN, AIN_KP);
    gemm_ca<true, false, true, false><<<dim3(2, (N_ATOMS + 127) / 128), 256, gsm>>>(
        AIN, WoR, W_o_b, nullptr, ah, N_ATOMS, AIN_KP, HIDDEN);

    // ---- per-molecule mean pool ----
    cudaMemsetAsync(sums, 0, (size_t)N_MOLS * HIDDEN * sizeof(float));
    cudaMemsetAsync(cnt,  0, (size_t)N_MOLS * sizeof(float));
    seg_kernel<<<segBlocks, 256>>>(ah, atom2mol, sums, cnt);
    divide_kernel<<<(N_MOLS * HIDDEN + 255) / 256, 256>>>(sums, cnt, molvec);

    // ---- FFNN ----
    pack2_kernel<<<(N_MOLS * (X_KP / 4) + 255) / 256, 256>>>(
        X, molvec, mol_features, N_MOLS, HIDDEN, MOL_FEAT, X_KP);
    gemm_ca<true, false, true, true><<<dim3(4, N_MOLS / 128), 256, gsm>>>(
        X, W1R, b1, nullptr, hid, N_MOLS, X_KP, FFNN_HID);
    gemm_ca<true, false, true, false><<<dim3(2, N_MOLS / 128), 256, gsm>>>(
        hid, W2R, b2, nullptr, out, N_MOLS, FFNN_HID, ENC_HID);
}